// round 2
// baseline (speedup 1.0000x reference)
#include <cuda_runtime.h>

#define T_STEPS 512
#define BATCH   64
#define DIN     256
#define DH      1024
#define DOUT    256
#define BH      (BATCH * DH)      // 65536
#define SCAN_CTAS 128
#define NC        8               // columns of W_h per CTA

// Scratch (device globals: allocation-free per harness rules)
__device__ float g_xp[T_STEPS * BH];       // [T][B][H] input projection
__device__ float g_hs[T_STEPS * BH];       // [T][B][H] hidden states
__device__ unsigned int g_bar[T_STEPS];    // per-step grid barrier counters

// ---------------------------------------------------------------------------
// Kernel A: x_proj[t][b][h] = sum_i inputs[b][t][i] * W_in[i][h] + bias[h]
// grid (T, 16), block 256, tile M=64(all b of one t) x N=64, Kt=32
// ---------------------------------------------------------------------------
__global__ void k_xproj(const float* __restrict__ x,
                        const float* __restrict__ Wi,
                        const float* __restrict__ bias) {
    const int t  = blockIdx.x;
    const int n0 = blockIdx.y * 64;
    __shared__ float As[64][36];
    __shared__ float Bs[32][68];
    const int tid = threadIdx.x;
    const int ty = tid >> 4, tx = tid & 15;
    float acc[4][4] = {};

    for (int k0 = 0; k0 < DIN; k0 += 32) {
        for (int i = tid; i < 64 * 32; i += 256) {
            int m = i >> 5, kk = i & 31;
            As[m][kk] = x[(m * T_STEPS + t) * DIN + k0 + kk];
        }
        for (int i = tid; i < 32 * 64; i += 256) {
            int kk = i >> 6, n = i & 63;
            Bs[kk][n] = Wi[(k0 + kk) * DH + n0 + n];
        }
        __syncthreads();
#pragma unroll
        for (int kk = 0; kk < 32; kk++) {
            float4 b = *(const float4*)&Bs[kk][tx * 4];
            float a0 = As[ty * 4 + 0][kk];
            float a1 = As[ty * 4 + 1][kk];
            float a2 = As[ty * 4 + 2][kk];
            float a3 = As[ty * 4 + 3][kk];
            acc[0][0] = fmaf(a0, b.x, acc[0][0]); acc[0][1] = fmaf(a0, b.y, acc[0][1]);
            acc[0][2] = fmaf(a0, b.z, acc[0][2]); acc[0][3] = fmaf(a0, b.w, acc[0][3]);
            acc[1][0] = fmaf(a1, b.x, acc[1][0]); acc[1][1] = fmaf(a1, b.y, acc[1][1]);
            acc[1][2] = fmaf(a1, b.z, acc[1][2]); acc[1][3] = fmaf(a1, b.w, acc[1][3]);
            acc[2][0] = fmaf(a2, b.x, acc[2][0]); acc[2][1] = fmaf(a2, b.y, acc[2][1]);
            acc[2][2] = fmaf(a2, b.z, acc[2][2]); acc[2][3] = fmaf(a2, b.w, acc[2][3]);
            acc[3][0] = fmaf(a3, b.x, acc[3][0]); acc[3][1] = fmaf(a3, b.y, acc[3][1]);
            acc[3][2] = fmaf(a3, b.z, acc[3][2]); acc[3][3] = fmaf(a3, b.w, acc[3][3]);
        }
        __syncthreads();
    }
    float4 bv = *(const float4*)&bias[n0 + tx * 4];
#pragma unroll
    for (int i = 0; i < 4; i++) {
        float4 v;
        v.x = acc[i][0] + bv.x; v.y = acc[i][1] + bv.y;
        v.z = acc[i][2] + bv.z; v.w = acc[i][3] + bv.w;
        *(float4*)&g_xp[t * BH + (ty * 4 + i) * DH + n0 + tx * 4] = v;
    }
}

// ---------------------------------------------------------------------------
// Kernel B: persistent recurrent scan.
// grid SCAN_CTAS=128, block 256. CTA c owns output columns [8c, 8c+8).
// W_h column slice cached in SMEM for all 512 steps.
// Grid barrier per step via per-step counters with deferred reset.
// ---------------------------------------------------------------------------
__device__ __forceinline__ void grid_barrier(int t) {
    __syncthreads();
    if (threadIdx.x == 0) {
        __threadfence();                    // publish hs[t] stores
        atomicAdd(&g_bar[t], 1u);
        while (((volatile unsigned int*)g_bar)[t] < gridDim.x) { }
        __threadfence();                    // acquire others' stores
        if (blockIdx.x == 0 && t > 0) g_bar[t - 1] = 0;  // safe: all passed t-1
    }
    __syncthreads();
}

#define KT 256  // k-tile of h staged in smem per inner iteration

__global__ void k_scan(const float* __restrict__ Wh) {
    extern __shared__ float smem[];
    float* sW = smem;                 // [NC][1028] j-major W_h columns
    float* sH = smem + NC * 1028;     // [64][260]  h tile (padded, 16B-aligned rows)

    const int tid = threadIdx.x;
    const int n0  = blockIdx.x * NC;

    // reset leftover counter from previous launch (before any barrier use)
    if (blockIdx.x == 0 && tid == 0) g_bar[T_STEPS - 1] = 0;

    // Load this CTA's W_h columns once: sW[j][k] = Wh[k][n0+j]
    for (int i = tid; i < NC * DH; i += 256) {
        int j = i & (NC - 1);
        int k = i >> 3;
        sW[j * 1028 + k] = Wh[k * DH + n0 + j];
    }
    __syncthreads();

    const int m  = tid >> 2;          // 0..63 (batch row)
    const int jp = (tid & 3) * 2;     // 0,2,4,6 (pair of columns)
    const float* wj0 = sW + jp * 1028;
    const float* wj1 = wj0 + 1028;
    const float* hrow = sH + m * 260;

    for (int t = 0; t < T_STEPS; t++) {
        const float xv0 = g_xp[t * BH + m * DH + n0 + jp];
        const float xv1 = g_xp[t * BH + m * DH + n0 + jp + 1];
        float4 a0 = {0.f, 0.f, 0.f, 0.f};
        float4 a1 = {0.f, 0.f, 0.f, 0.f};

        if (t > 0) {
            const float* __restrict__ hprev = g_hs + (t - 1) * BH;
            for (int k0 = 0; k0 < DH; k0 += KT) {
                // stage h tile [64][KT] (float4 coalesced)
                for (int i = tid; i < 64 * (KT / 4); i += 256) {
                    int mm = i >> 6;
                    int kv = i & 63;
                    *(float4*)(sH + mm * 260 + kv * 4) =
                        *(const float4*)(hprev + mm * DH + k0 + kv * 4);
                }
                __syncthreads();
                const float* w0p = wj0 + k0;
                const float* w1p = wj1 + k0;
#pragma unroll 8
                for (int kk = 0; kk < KT; kk += 4) {
                    float4 hv = *(const float4*)(hrow + kk);
                    float4 w0 = *(const float4*)(w0p + kk);
                    float4 w1 = *(const float4*)(w1p + kk);
                    a0.x = fmaf(hv.x, w0.x, a0.x);
                    a0.y = fmaf(hv.y, w0.y, a0.y);
                    a0.z = fmaf(hv.z, w0.z, a0.z);
                    a0.w = fmaf(hv.w, w0.w, a0.w);
                    a1.x = fmaf(hv.x, w1.x, a1.x);
                    a1.y = fmaf(hv.y, w1.y, a1.y);
                    a1.z = fmaf(hv.z, w1.z, a1.z);
                    a1.w = fmaf(hv.w, w1.w, a1.w);
                }
                __syncthreads();
            }
        }

        float h0 = tanhf(xv0 + ((a0.x + a0.y) + (a0.z + a0.w)));
        float h1 = tanhf(xv1 + ((a1.x + a1.y) + (a1.z + a1.w)));
        float2 hv2; hv2.x = h0; hv2.y = h1;
        *(float2*)&g_hs[t * BH + m * DH + n0 + jp] = hv2;

        grid_barrier(t);
    }
}

// ---------------------------------------------------------------------------
// Kernel C: out[b][t][o] = sum_h hs[t][b][h] * W_out[h][o] + bias[o]
// grid (T, 4), block 256, tile 64x64, K=1024
// ---------------------------------------------------------------------------
__global__ void k_out(const float* __restrict__ Wo,
                      const float* __restrict__ bias,
                      float* __restrict__ out) {
    const int t  = blockIdx.x;
    const int n0 = blockIdx.y * 64;
    __shared__ float As[64][36];
    __shared__ float Bs[32][68];
    const int tid = threadIdx.x;
    const int ty = tid >> 4, tx = tid & 15;
    float acc[4][4] = {};

    for (int k0 = 0; k0 < DH; k0 += 32) {
        for (int i = tid; i < 64 * 32; i += 256) {
            int m = i >> 5, kk = i & 31;
            As[m][kk] = g_hs[t * BH + m * DH + k0 + kk];
        }
        for (int i = tid; i < 32 * 64; i += 256) {
            int kk = i >> 6, n = i & 63;
            Bs[kk][n] = Wo[(k0 + kk) * DOUT + n0 + n];
        }
        __syncthreads();
#pragma unroll
        for (int kk = 0; kk < 32; kk++) {
            float4 b = *(const float4*)&Bs[kk][tx * 4];
            float a0 = As[ty * 4 + 0][kk];
            float a1 = As[ty * 4 + 1][kk];
            float a2 = As[ty * 4 + 2][kk];
            float a3 = As[ty * 4 + 3][kk];
            acc[0][0] = fmaf(a0, b.x, acc[0][0]); acc[0][1] = fmaf(a0, b.y, acc[0][1]);
            acc[0][2] = fmaf(a0, b.z, acc[0][2]); acc[0][3] = fmaf(a0, b.w, acc[0][3]);
            acc[1][0] = fmaf(a1, b.x, acc[1][0]); acc[1][1] = fmaf(a1, b.y, acc[1][1]);
            acc[1][2] = fmaf(a1, b.z, acc[1][2]); acc[1][3] = fmaf(a1, b.w, acc[1][3]);
            acc[2][0] = fmaf(a2, b.x, acc[2][0]); acc[2][1] = fmaf(a2, b.y, acc[2][1]);
            acc[2][2] = fmaf(a2, b.z, acc[2][2]); acc[2][3] = fmaf(a2, b.w, acc[2][3]);
            acc[3][0] = fmaf(a3, b.x, acc[3][0]); acc[3][1] = fmaf(a3, b.y, acc[3][1]);
            acc[3][2] = fmaf(a3, b.z, acc[3][2]); acc[3][3] = fmaf(a3, b.w, acc[3][3]);
        }
        __syncthreads();
    }
    float4 bv = *(const float4*)&bias[n0 + tx * 4];
#pragma unroll
    for (int i = 0; i < 4; i++) {
        float4 v;
        v.x = acc[i][0] + bv.x; v.y = acc[i][1] + bv.y;
        v.z = acc[i][2] + bv.z; v.w = acc[i][3] + bv.w;
        *(float4*)&out[((ty * 4 + i) * T_STEPS + t) * DOUT + n0 + tx * 4] = v;
    }
}

// ---------------------------------------------------------------------------
extern "C" void kernel_launch(void* const* d_in, const int* in_sizes, int n_in,
                              void* d_out, int out_size) {
    const float* x  = (const float*)d_in[0];  // inputs [B,T,DIN]
    const float* Wi = (const float*)d_in[1];  // input_kernel [DIN,DH]
    const float* Wh = (const float*)d_in[2];  // hidden_kernel [DH,DH]
    const float* bh = (const float*)d_in[3];  // hidden_bias [DH]
    const float* Wo = (const float*)d_in[4];  // output_kernel [DH,DOUT]
    const float* bo = (const float*)d_in[5];  // output_bias [DOUT]
    float* out = (float*)d_out;               // [B,T,DOUT]

    const int scan_smem = (NC * 1028 + 64 * 260) * (int)sizeof(float); // 99456 B
    cudaFuncSetAttribute(k_scan, cudaFuncAttributeMaxDynamicSharedMemorySize,
                         scan_smem);

    k_xproj<<<dim3(T_STEPS, DH / 64), 256>>>(x, Wi, bh);
    k_scan<<<SCAN_CTAS, 256, scan_smem>>>(Wh);
    k_out<<<dim3(T_STEPS, DOUT / 64), 256>>>(Wo, bo, out);
}

// round 3
// speedup vs baseline: 2.3591x; 2.3591x over previous
#include <cuda_runtime.h>

#define T_STEPS 512
#define BATCH   64
#define DIN     256
#define DH      1024
#define DOUT    256
#define BH      (BATCH * DH)      // 65536
#define SCAN_CTAS 128

typedef unsigned long long ull;

// Scratch (device globals: allocation-free per harness rules)
__device__ float g_xp[T_STEPS * BH];       // [T][B][H] input projection
__device__ float g_hs[T_STEPS * BH];       // [T][B][H] hidden states
__device__ unsigned int g_bar[T_STEPS];    // per-step grid barrier counters

// ---- packed f32x2 helpers -------------------------------------------------
__device__ __forceinline__ ull pack2(float x) {
    ull r;
    asm("mov.b64 %0, {%1, %1};" : "=l"(r) : "f"(x));
    return r;
}
__device__ __forceinline__ void fma2(ull& acc, ull a, ull b) {
    asm("fma.rn.f32x2 %0, %1, %2, %0;" : "+l"(acc) : "l"(a), "l"(b));
}
__device__ __forceinline__ ull add2(ull a, ull b) {
    ull d;
    asm("add.rn.f32x2 %0, %1, %2;" : "=l"(d) : "l"(a), "l"(b));
    return d;
}
__device__ __forceinline__ void unpack2(ull v, float& lo, float& hi) {
    asm("mov.b64 {%0, %1}, %2;" : "=f"(lo), "=f"(hi) : "l"(v));
}

// ---------------------------------------------------------------------------
// Kernel A: x_proj[t][b][h] = sum_i inputs[b][t][i] * W_in[i][h] + bias[h]
// ---------------------------------------------------------------------------
__global__ void k_xproj(const float* __restrict__ x,
                        const float* __restrict__ Wi,
                        const float* __restrict__ bias) {
    const int t  = blockIdx.x;
    const int n0 = blockIdx.y * 64;
    __shared__ __align__(16) float As[64][36];
    __shared__ __align__(16) float Bs[32][68];
    const int tid = threadIdx.x;
    const int ty = tid >> 4, tx = tid & 15;
    ull acc[4][2] = {};

    for (int k0 = 0; k0 < DIN; k0 += 32) {
        for (int i = tid; i < 64 * 32; i += 256) {
            int m = i >> 5, kk = i & 31;
            As[m][kk] = x[(m * T_STEPS + t) * DIN + k0 + kk];
        }
        for (int i = tid; i < 32 * 64; i += 256) {
            int kk = i >> 6, n = i & 63;
            Bs[kk][n] = Wi[(k0 + kk) * DH + n0 + n];
        }
        __syncthreads();
#pragma unroll
        for (int kk = 0; kk < 32; kk++) {
            ulonglong2 bb = *(const ulonglong2*)&Bs[kk][tx * 4];
#pragma unroll
            for (int i = 0; i < 4; i++) {
                ull pa = pack2(As[ty * 4 + i][kk]);
                fma2(acc[i][0], pa, bb.x);
                fma2(acc[i][1], pa, bb.y);
            }
        }
        __syncthreads();
    }
    float4 bv = *(const float4*)&bias[n0 + tx * 4];
#pragma unroll
    for (int i = 0; i < 4; i++) {
        float4 v;
        unpack2(acc[i][0], v.x, v.y);
        unpack2(acc[i][1], v.z, v.w);
        v.x += bv.x; v.y += bv.y; v.z += bv.z; v.w += bv.w;
        *(float4*)&g_xp[t * BH + (ty * 4 + i) * DH + n0 + tx * 4] = v;
    }
}

// ---------------------------------------------------------------------------
// Kernel B: persistent recurrent scan, W_h in registers, f32x2 FMA.
// 128 CTAs x 256 thr. CTA owns 8 cols x 64 rows. Warp w: rows 16*(w>>1),
// cols (w&1)*4 of the CTA's 8. Lane l owns k in {j*128 + 4l .. 4l+3}.
// ---------------------------------------------------------------------------
__device__ __forceinline__ void grid_barrier(int t) {
    __syncthreads();
    if (threadIdx.x == 0) {
        __threadfence();
        atomicAdd(&g_bar[t], 1u);
        while (((volatile unsigned int*)g_bar)[t] < (unsigned)gridDim.x) { }
        __threadfence();
        if (blockIdx.x == 0 && t > 0) g_bar[t - 1] = 0;
    }
    __syncthreads();
}

__global__ void __launch_bounds__(256, 1) k_scan(const float* __restrict__ Wh) {
    const int tid  = threadIdx.x;
    const int w    = tid >> 5;
    const int lane = tid & 31;
    const int row0 = (w >> 1) * 16;                       // warp's 16 rows
    const int col0 = blockIdx.x * 8 + (w & 1) * 4;        // warp's 4 cols

    if (blockIdx.x == 0 && tid == 0) g_bar[T_STEPS - 1] = 0;

    // W registers: W2[j][kv][c2] = packed cols (col0+2c2, col0+2c2+1)
    // at k = j*128 + lane*4 + kv.  64 x b64 = 128 regs, static-indexed.
    ull W2[8][4][2];
#pragma unroll
    for (int j = 0; j < 8; j++)
#pragma unroll
        for (int kv = 0; kv < 4; kv++) {
            int k = j * 128 + lane * 4 + kv;
            ulonglong2 wv = *(const ulonglong2*)&Wh[k * DH + col0];
            W2[j][kv][0] = wv.x;
            W2[j][kv][1] = wv.y;
        }

    // Output mapping after reduction: lane -> (m_i = lane>>1, c2 = lane&1)
    const int orow = row0 + (lane >> 1);
    const int ocol = col0 + (lane & 1) * 2;

    // t = 0: h = tanh(xp)
    {
        float2 xv = *(const float2*)&g_xp[orow * DH + ocol];
        float2 hv;
        hv.x = tanhf(xv.x);
        hv.y = tanhf(xv.y);
        *(float2*)&g_hs[orow * DH + ocol] = hv;
    }
    grid_barrier(0);

    for (int t = 1; t < T_STEPS; t++) {
        ull acc[16][2] = {};
        const float* __restrict__ hp = g_hs + (t - 1) * BH;

#pragma unroll
        for (int mi = 0; mi < 16; mi++) {
            const float* hrow = hp + (row0 + mi) * DH + lane * 4;
#pragma unroll
            for (int j = 0; j < 8; j++) {
                float4 hv = *(const float4*)(hrow + j * 128);
                ull h0 = pack2(hv.x), h1 = pack2(hv.y);
                ull h2 = pack2(hv.z), h3 = pack2(hv.w);
                fma2(acc[mi][0], h0, W2[j][0][0]); fma2(acc[mi][1], h0, W2[j][0][1]);
                fma2(acc[mi][0], h1, W2[j][1][0]); fma2(acc[mi][1], h1, W2[j][1][1]);
                fma2(acc[mi][0], h2, W2[j][2][0]); fma2(acc[mi][1], h2, W2[j][2][1]);
                fma2(acc[mi][0], h3, W2[j][3][0]); fma2(acc[mi][1], h3, W2[j][3][1]);
            }
        }

        // cross-lane reduce (each output summed over 32 lanes' k-slices)
        bool up;
        up = (lane & 16) != 0;
#pragma unroll
        for (int i = 0; i < 8; i++)
#pragma unroll
            for (int c = 0; c < 2; c++) {
                ull send = up ? acc[i][c] : acc[i + 8][c];
                ull recv = __shfl_xor_sync(0xffffffffu, send, 16);
                ull keep = up ? acc[i + 8][c] : acc[i][c];
                acc[i][c] = add2(keep, recv);
            }
        up = (lane & 8) != 0;
#pragma unroll
        for (int i = 0; i < 4; i++)
#pragma unroll
            for (int c = 0; c < 2; c++) {
                ull send = up ? acc[i][c] : acc[i + 4][c];
                ull recv = __shfl_xor_sync(0xffffffffu, send, 8);
                ull keep = up ? acc[i + 4][c] : acc[i][c];
                acc[i][c] = add2(keep, recv);
            }
        up = (lane & 4) != 0;
#pragma unroll
        for (int i = 0; i < 2; i++)
#pragma unroll
            for (int c = 0; c < 2; c++) {
                ull send = up ? acc[i][c] : acc[i + 2][c];
                ull recv = __shfl_xor_sync(0xffffffffu, send, 4);
                ull keep = up ? acc[i + 2][c] : acc[i][c];
                acc[i][c] = add2(keep, recv);
            }
        up = (lane & 2) != 0;
#pragma unroll
        for (int c = 0; c < 2; c++) {
            ull send = up ? acc[0][c] : acc[1][c];
            ull recv = __shfl_xor_sync(0xffffffffu, send, 2);
            ull keep = up ? acc[1][c] : acc[0][c];
            acc[0][c] = add2(keep, recv);
        }
        up = (lane & 1) != 0;
        {
            ull send = up ? acc[0][0] : acc[0][1];
            ull recv = __shfl_xor_sync(0xffffffffu, send, 1);
            ull keep = up ? acc[0][1] : acc[0][0];
            acc[0][0] = add2(keep, recv);
        }

        float s0, s1;
        unpack2(acc[0][0], s0, s1);
        float2 xv = *(const float2*)&g_xp[t * BH + orow * DH + ocol];
        float2 hv;
        hv.x = tanhf(xv.x + s0);
        hv.y = tanhf(xv.y + s1);
        *(float2*)&g_hs[t * BH + orow * DH + ocol] = hv;

        grid_barrier(t);
    }
}

// ---------------------------------------------------------------------------
// Kernel C: out[b][t][o] = sum_h hs[t][b][h] * W_out[h][o] + bias[o]
// ---------------------------------------------------------------------------
__global__ void k_out(const float* __restrict__ Wo,
                      const float* __restrict__ bias,
                      float* __restrict__ out) {
    const int t  = blockIdx.x;
    const int n0 = blockIdx.y * 64;
    __shared__ __align__(16) float As[64][36];
    __shared__ __align__(16) float Bs[32][68];
    const int tid = threadIdx.x;
    const int ty = tid >> 4, tx = tid & 15;
    ull acc[4][2] = {};

    for (int k0 = 0; k0 < DH; k0 += 32) {
        for (int i = tid; i < 64 * 32; i += 256) {
            int m = i >> 5, kk = i & 31;
            As[m][kk] = g_hs[t * BH + m * DH + k0 + kk];
        }
        for (int i = tid; i < 32 * 64; i += 256) {
            int kk = i >> 6, n = i & 63;
            Bs[kk][n] = Wo[(k0 + kk) * DOUT + n0 + n];
        }
        __syncthreads();
#pragma unroll
        for (int kk = 0; kk < 32; kk++) {
            ulonglong2 bb = *(const ulonglong2*)&Bs[kk][tx * 4];
#pragma unroll
            for (int i = 0; i < 4; i++) {
                ull pa = pack2(As[ty * 4 + i][kk]);
                fma2(acc[i][0], pa, bb.x);
                fma2(acc[i][1], pa, bb.y);
            }
        }
        __syncthreads();
    }
    float4 bv = *(const float4*)&bias[n0 + tx * 4];
#pragma unroll
    for (int i = 0; i < 4; i++) {
        float4 v;
        unpack2(acc[i][0], v.x, v.y);
        unpack2(acc[i][1], v.z, v.w);
        v.x += bv.x; v.y += bv.y; v.z += bv.z; v.w += bv.w;
        *(float4*)&out[((ty * 4 + i) * T_STEPS + t) * DOUT + n0 + tx * 4] = v;
    }
}

// ---------------------------------------------------------------------------
extern "C" void kernel_launch(void* const* d_in, const int* in_sizes, int n_in,
                              void* d_out, int out_size) {
    const float* x  = (const float*)d_in[0];  // inputs [B,T,DIN]
    const float* Wi = (const float*)d_in[1];  // input_kernel [DIN,DH]
    const float* Wh = (const float*)d_in[2];  // hidden_kernel [DH,DH]
    const float* bh = (const float*)d_in[3];  // hidden_bias [DH]
    const float* Wo = (const float*)d_in[4];  // output_kernel [DH,DOUT]
    const float* bo = (const float*)d_in[5];  // output_bias [DOUT]
    float* out = (float*)d_out;               // [B,T,DOUT]

    k_xproj<<<dim3(T_STEPS, DH / 64), 256>>>(x, Wi, bh);
    k_scan<<<SCAN_CTAS, 256>>>(Wh);
    k_out<<<dim3(T_STEPS, DOUT / 64), 256>>>(Wo, bo, out);
}

// round 4
// speedup vs baseline: 2.4139x; 1.0233x over previous
#include <cuda_runtime.h>

#define T_STEPS 512
#define BATCH   64
#define DIN     256
#define DH      1024
#define DOUT    256
#define BH      (BATCH * DH)      // 65536
#define SCAN_CTAS 128

typedef unsigned long long ull;

// Scratch (device globals: allocation-free per harness rules)
__device__ float g_xp[T_STEPS * BH];       // [T][B][H] input projection
__device__ float g_hs[T_STEPS * BH];       // [T][B][H] hidden states
__device__ unsigned int g_bar[T_STEPS];    // per-step grid barrier counters

// ---- packed f32x2 helpers -------------------------------------------------
__device__ __forceinline__ ull pack2(float x) {
    ull r;
    asm("mov.b64 %0, {%1, %1};" : "=l"(r) : "f"(x));
    return r;
}
__device__ __forceinline__ void fma2(ull& acc, ull a, ull b) {
    asm("fma.rn.f32x2 %0, %1, %2, %0;" : "+l"(acc) : "l"(a), "l"(b));
}
__device__ __forceinline__ ull add2(ull a, ull b) {
    ull d;
    asm("add.rn.f32x2 %0, %1, %2;" : "=l"(d) : "l"(a), "l"(b));
    return d;
}
__device__ __forceinline__ void unpack2(ull v, float& lo, float& hi) {
    asm("mov.b64 {%0, %1}, %2;" : "=f"(lo), "=f"(hi) : "l"(v));
}

// ---------------------------------------------------------------------------
// Kernel A: x_proj[t][b][h] = sum_i inputs[b][t][i] * W_in[i][h] + bias[h]
// ---------------------------------------------------------------------------
__global__ void k_xproj(const float* __restrict__ x,
                        const float* __restrict__ Wi,
                        const float* __restrict__ bias) {
    const int t  = blockIdx.x;
    const int n0 = blockIdx.y * 64;
    __shared__ __align__(16) float As[64][36];
    __shared__ __align__(16) float Bs[32][68];
    const int tid = threadIdx.x;
    const int ty = tid >> 4, tx = tid & 15;
    ull acc[4][2] = {};

    for (int k0 = 0; k0 < DIN; k0 += 32) {
        for (int i = tid; i < 64 * 32; i += 256) {
            int m = i >> 5, kk = i & 31;
            As[m][kk] = x[(m * T_STEPS + t) * DIN + k0 + kk];
        }
        for (int i = tid; i < 32 * 64; i += 256) {
            int kk = i >> 6, n = i & 63;
            Bs[kk][n] = Wi[(k0 + kk) * DH + n0 + n];
        }
        __syncthreads();
#pragma unroll
        for (int kk = 0; kk < 32; kk++) {
            ulonglong2 bb = *(const ulonglong2*)&Bs[kk][tx * 4];
#pragma unroll
            for (int i = 0; i < 4; i++) {
                ull pa = pack2(As[ty * 4 + i][kk]);
                fma2(acc[i][0], pa, bb.x);
                fma2(acc[i][1], pa, bb.y);
            }
        }
        __syncthreads();
    }
    float4 bv = *(const float4*)&bias[n0 + tx * 4];
#pragma unroll
    for (int i = 0; i < 4; i++) {
        float4 v;
        unpack2(acc[i][0], v.x, v.y);
        unpack2(acc[i][1], v.z, v.w);
        v.x += bv.x; v.y += bv.y; v.z += bv.z; v.w += bv.w;
        *(float4*)&g_xp[t * BH + (ty * 4 + i) * DH + n0 + tx * 4] = v;
    }
}

// ---------------------------------------------------------------------------
// Kernel B: persistent recurrent scan, W_h in registers, f32x2 FMA.
// 128 CTAs x 256 thr. CTA tile: 16 rows x 32 cols (rb = bid>>5, cb = bid&31).
// Warp w owns cols cb*32 + 4w (4 cols); lane owns a scrambled 32-float K slice.
// Chip L2 traffic per step: 128 x 64KB = 8MB (vs 32MB with 8-col CTAs).
// ---------------------------------------------------------------------------
__device__ __forceinline__ void grid_barrier(int t) {
    __syncthreads();
    if (threadIdx.x == 0) {
        __threadfence();
        atomicAdd(&g_bar[t], 1u);
        while (((volatile unsigned int*)g_bar)[t] < (unsigned)gridDim.x) { }
        __threadfence();
        if (blockIdx.x == 0 && t > 0) g_bar[t - 1] = 0;
    }
    __syncthreads();
}

__global__ void __launch_bounds__(256, 1) k_scan(const float* __restrict__ Wh) {
    const int tid  = threadIdx.x;
    const int w    = tid >> 5;
    const int lane = tid & 31;
    const int rb   = blockIdx.x >> 5;          // 0..3
    const int cb   = blockIdx.x & 31;          // 0..31
    const int row0 = rb * 16;                  // CTA's 16 rows
    const int col0 = cb * 32 + w * 4;          // warp's 4 cols
    // scrambled K assignment (uniform within warp, varies per CTA):
    const int klane = (lane + blockIdx.x) & 31;

    if (blockIdx.x == 0 && tid == 0) g_bar[T_STEPS - 1] = 0;

    // W registers: W2[j][kv][c2] = packed cols (col0+2c2, col0+2c2+1)
    // at k = j*128 + klane*4 + kv.  64 x b64 = 128 regs, static-indexed.
    ull W2[8][4][2];
#pragma unroll
    for (int j = 0; j < 8; j++)
#pragma unroll
        for (int kv = 0; kv < 4; kv++) {
            int k = j * 128 + klane * 4 + kv;
            ulonglong2 wv = *(const ulonglong2*)&Wh[k * DH + col0];
            W2[j][kv][0] = wv.x;
            W2[j][kv][1] = wv.y;
        }

    // Output mapping after reduction: lane -> (row = lane>>1, colpair = lane&1)
    const int orow = row0 + (lane >> 1);
    const int ocol = col0 + (lane & 1) * 2;

    // t = 0: h = tanh(xp)
    {
        float2 xv = *(const float2*)&g_xp[orow * DH + ocol];
        float2 hv;
        hv.x = tanhf(xv.x);
        hv.y = tanhf(xv.y);
        *(float2*)&g_hs[orow * DH + ocol] = hv;
    }
    grid_barrier(0);

    for (int t = 1; t < T_STEPS; t++) {
        // prefetch this step's xp early (independent of h)
        float2 xv = *(const float2*)&g_xp[t * BH + orow * DH + ocol];

        ull acc[16][2] = {};
        const float* __restrict__ hp = g_hs + (t - 1) * BH;

#pragma unroll
        for (int mi = 0; mi < 16; mi++) {
            const float* hrow = hp + (row0 + mi) * DH + klane * 4;
#pragma unroll
            for (int j = 0; j < 8; j++) {
                float4 hv = *(const float4*)(hrow + j * 128);
                ull h0 = pack2(hv.x), h1 = pack2(hv.y);
                ull h2 = pack2(hv.z), h3 = pack2(hv.w);
                fma2(acc[mi][0], h0, W2[j][0][0]); fma2(acc[mi][1], h0, W2[j][0][1]);
                fma2(acc[mi][0], h1, W2[j][1][0]); fma2(acc[mi][1], h1, W2[j][1][1]);
                fma2(acc[mi][0], h2, W2[j][2][0]); fma2(acc[mi][1], h2, W2[j][2][1]);
                fma2(acc[mi][0], h3, W2[j][3][0]); fma2(acc[mi][1], h3, W2[j][3][1]);
            }
        }

        // cross-lane reduce (each output summed over 32 lanes' k-slices)
        bool up;
        up = (lane & 16) != 0;
#pragma unroll
        for (int i = 0; i < 8; i++)
#pragma unroll
            for (int c = 0; c < 2; c++) {
                ull send = up ? acc[i][c] : acc[i + 8][c];
                ull recv = __shfl_xor_sync(0xffffffffu, send, 16);
                ull keep = up ? acc[i + 8][c] : acc[i][c];
                acc[i][c] = add2(keep, recv);
            }
        up = (lane & 8) != 0;
#pragma unroll
        for (int i = 0; i < 4; i++)
#pragma unroll
            for (int c = 0; c < 2; c++) {
                ull send = up ? acc[i][c] : acc[i + 4][c];
                ull recv = __shfl_xor_sync(0xffffffffu, send, 8);
                ull keep = up ? acc[i + 4][c] : acc[i][c];
                acc[i][c] = add2(keep, recv);
            }
        up = (lane & 4) != 0;
#pragma unroll
        for (int i = 0; i < 2; i++)
#pragma unroll
            for (int c = 0; c < 2; c++) {
                ull send = up ? acc[i][c] : acc[i + 2][c];
                ull recv = __shfl_xor_sync(0xffffffffu, send, 4);
                ull keep = up ? acc[i + 2][c] : acc[i][c];
                acc[i][c] = add2(keep, recv);
            }
        up = (lane & 2) != 0;
#pragma unroll
        for (int c = 0; c < 2; c++) {
            ull send = up ? acc[0][c] : acc[1][c];
            ull recv = __shfl_xor_sync(0xffffffffu, send, 2);
            ull keep = up ? acc[1][c] : acc[0][c];
            acc[0][c] = add2(keep, recv);
        }
        up = (lane & 1) != 0;
        {
            ull send = up ? acc[0][0] : acc[0][1];
            ull recv = __shfl_xor_sync(0xffffffffu, send, 1);
            ull keep = up ? acc[0][1] : acc[0][0];
            acc[0][0] = add2(keep, recv);
        }

        float s0, s1;
        unpack2(acc[0][0], s0, s1);
        float2 hv;
        hv.x = tanhf(xv.x + s0);
        hv.y = tanhf(xv.y + s1);
        *(float2*)&g_hs[t * BH + orow * DH + ocol] = hv;

        grid_barrier(t);
    }
}

// ---------------------------------------------------------------------------
// Kernel C: out[b][t][o] = sum_h hs[t][b][h] * W_out[h][o] + bias[o]
// ---------------------------------------------------------------------------
__global__ void k_out(const float* __restrict__ Wo,
                      const float* __restrict__ bias,
                      float* __restrict__ out) {
    const int t  = blockIdx.x;
    const int n0 = blockIdx.y * 64;
    __shared__ __align__(16) float As[64][36];
    __shared__ __align__(16) float Bs[32][68];
    const int tid = threadIdx.x;
    const int ty = tid >> 4, tx = tid & 15;
    ull acc[4][2] = {};

    for (int k0 = 0; k0 < DH; k0 += 32) {
        for (int i = tid; i < 64 * 32; i += 256) {
            int m = i >> 5, kk = i & 31;
            As[m][kk] = g_hs[t * BH + m * DH + k0 + kk];
        }
        for (int i = tid; i < 32 * 64; i += 256) {
            int kk = i >> 6, n = i & 63;
            Bs[kk][n] = Wo[(k0 + kk) * DOUT + n0 + n];
        }
        __syncthreads();
#pragma unroll
        for (int kk = 0; kk < 32; kk++) {
            ulonglong2 bb = *(const ulonglong2*)&Bs[kk][tx * 4];
#pragma unroll
            for (int i = 0; i < 4; i++) {
                ull pa = pack2(As[ty * 4 + i][kk]);
                fma2(acc[i][0], pa, bb.x);
                fma2(acc[i][1], pa, bb.y);
            }
        }
        __syncthreads();
    }
    float4 bv = *(const float4*)&bias[n0 + tx * 4];
#pragma unroll
    for (int i = 0; i < 4; i++) {
        float4 v;
        unpack2(acc[i][0], v.x, v.y);
        unpack2(acc[i][1], v.z, v.w);
        v.x += bv.x; v.y += bv.y; v.z += bv.z; v.w += bv.w;
        *(float4*)&out[((ty * 4 + i) * T_STEPS + t) * DOUT + n0 + tx * 4] = v;
    }
}

// ---------------------------------------------------------------------------
extern "C" void kernel_launch(void* const* d_in, const int* in_sizes, int n_in,
                              void* d_out, int out_size) {
    const float* x  = (const float*)d_in[0];  // inputs [B,T,DIN]
    const float* Wi = (const float*)d_in[1];  // input_kernel [DIN,DH]
    const float* Wh = (const float*)d_in[2];  // hidden_kernel [DH,DH]
    const float* bh = (const float*)d_in[3];  // hidden_bias [DH]
    const float* Wo = (const float*)d_in[4];  // output_kernel [DH,DOUT]
    const float* bo = (const float*)d_in[5];  // output_bias [DOUT]
    float* out = (float*)d_out;               // [B,T,DOUT]

    k_xproj<<<dim3(T_STEPS, DH / 64), 256>>>(x, Wi, bh);
    k_scan<<<SCAN_CTAS, 256>>>(Wh);
    k_out<<<dim3(T_STEPS, DOUT / 64), 256>>>(Wo, bo, out);
}